// round 16
// baseline (speedup 1.0000x reference)
#include <cuda_runtime.h>
#include <cuda_fp16.h>
#include <math.h>
#include <stdint.h>

// Problem constants
#define VOCAB 50257
#define NPAD  50432              // 197 * 256
#define DMODEL 128
#define HID 256
#define BATCH 16
#define SEQ 128
#define GATES (3*HID)            // 768
#define MTOK (BATCH*SEQ)         // 2048

// Scratch (__device__ globals per allocation-free rule)
__device__ float g_gx[MTOK * GATES];          // input-side gate projections
__device__ __half g_a2[MTOK * HID];           // fp16(h)    [2048,256]
__device__ __half g_b2[NPAD * HID];           // fp16(W_out)[50432,256]
__device__ float g_hbuf[2][BATCH * HID];      // double-buffered h exchange
__device__ int g_flags[16][32];               // per-group CTA arrival flags

__device__ __forceinline__ uint32_t smem_to_u32(const void* p) {
    uint32_t a;
    asm("{ .reg .u64 t; cvta.to.shared.u64 t, %1; cvt.u32.u64 %0, t; }"
        : "=r"(a) : "l"(p));
    return a;
}

// ---------------------------------------------------------------------------
// Stage 0+1 fused: CTAs 0..95 gather+bias TN SGEMM; CTAs 96..159 W_out->fp16.
// (proven, 50us)
// ---------------------------------------------------------------------------
#define FAT_GEMM_CTAS 96
#define FAT_CONV_CTAS 64

__global__ __launch_bounds__(256)
void fat_gemm_conv(const float* __restrict__ A, const int* __restrict__ idx,
                   const float* __restrict__ Bm, const float* __restrict__ bias,
                   float* __restrict__ C,
                   const float* __restrict__ W, __half* __restrict__ B2)
{
    constexpr int BM = 128, BN = 128, BK = 16;
    constexpr int K = DMODEL;
    __shared__ float As[BK][BM];
    __shared__ float Bs[BK][BN];

    const int tid = threadIdx.x;

    if (blockIdx.x >= FAT_GEMM_CTAS) {
        const int cidx = blockIdx.x - FAT_GEMM_CTAS;
        for (int i = cidx * 256 + tid; i < NPAD * 64; i += FAT_CONV_CTAS * 256) {
            int v = i >> 6;
            int k4 = (i & 63) * 4;
            __half2 h01, h23;
            if (v < VOCAB) {
                float4 x = *(const float4*)(W + (size_t)v * HID + k4);
                h01 = __halves2half2(__float2half_rn(x.x), __float2half_rn(x.y));
                h23 = __halves2half2(__float2half_rn(x.z), __float2half_rn(x.w));
            } else {
                h01 = h23 = __halves2half2(__float2half_rn(0.f), __float2half_rn(0.f));
            }
            __half2* row = (__half2*)(B2 + (size_t)v * HID);
            row[(k4 >> 1)]     = h01;
            row[(k4 >> 1) + 1] = h23;
        }
        return;
    }

    const int tx = tid & 15, ty = tid >> 4;
    const int m0 = (blockIdx.x / 6) * BM, n0 = (blockIdx.x % 6) * BN;

    int a_row[2], a_col[2], b_row[2], b_col[2];
    const float* a_src[2];
    const float* b_src[2];
#pragma unroll
    for (int i = 0; i < 2; i++) {
        int f = tid * 2 + i;
        int r = f >> 2, cv = (f & 3) * 4;
        a_row[i] = r; a_col[i] = cv;
        b_row[i] = r; b_col[i] = cv;
        int gm = m0 + r;
        int src_row = idx[gm];
        a_src[i] = A + (size_t)src_row * K + cv;
        int gn = n0 + r;
        b_src[i] = Bm + (size_t)gn * K + cv;
    }

    float acc[8][8];
#pragma unroll
    for (int i = 0; i < 8; i++)
#pragma unroll
        for (int j = 0; j < 8; j++) acc[i][j] = 0.f;

    const int ntiles = K / BK;
    float4 a_reg[2], b_reg[2];
#pragma unroll
    for (int i = 0; i < 2; i++) {
        a_reg[i] = *(const float4*)(a_src[i]);
        b_reg[i] = *(const float4*)(b_src[i]);
    }

    for (int kt = 0; kt < ntiles; kt++) {
#pragma unroll
        for (int i = 0; i < 2; i++) {
            As[a_col[i]+0][a_row[i]] = a_reg[i].x;
            As[a_col[i]+1][a_row[i]] = a_reg[i].y;
            As[a_col[i]+2][a_row[i]] = a_reg[i].z;
            As[a_col[i]+3][a_row[i]] = a_reg[i].w;
            Bs[b_col[i]+0][b_row[i]] = b_reg[i].x;
            Bs[b_col[i]+1][b_row[i]] = b_reg[i].y;
            Bs[b_col[i]+2][b_row[i]] = b_reg[i].z;
            Bs[b_col[i]+3][b_row[i]] = b_reg[i].w;
        }
        __syncthreads();

        if (kt + 1 < ntiles) {
            int koff = (kt + 1) * BK;
#pragma unroll
            for (int i = 0; i < 2; i++) {
                a_reg[i] = *(const float4*)(a_src[i] + koff);
                b_reg[i] = *(const float4*)(b_src[i] + koff);
            }
        }

#pragma unroll
        for (int k = 0; k < BK; k++) {
            float4 a0 = *(const float4*)&As[k][ty * 8];
            float4 a1 = *(const float4*)&As[k][ty * 8 + 4];
            float4 b0 = *(const float4*)&Bs[k][tx * 8];
            float4 b1 = *(const float4*)&Bs[k][tx * 8 + 4];
            float av[8] = {a0.x,a0.y,a0.z,a0.w,a1.x,a1.y,a1.z,a1.w};
            float bv[8] = {b0.x,b0.y,b0.z,b0.w,b1.x,b1.y,b1.z,b1.w};
#pragma unroll
            for (int i = 0; i < 8; i++)
#pragma unroll
                for (int j = 0; j < 8; j++)
                    acc[i][j] += av[i] * bv[j];
        }
        __syncthreads();
    }

#pragma unroll
    for (int i = 0; i < 8; i++) {
        int gm = m0 + ty * 8 + i;
        float* crow = C + (size_t)gm * GATES + n0 + tx * 8;
#pragma unroll
        for (int j = 0; j < 8; j++) {
            int gn = n0 + tx * 8 + j;
            crow[j] = acc[i][j] + bias[gn];
        }
    }
}

// ---------------------------------------------------------------------------
// Stage 2: GRU scan v6 (proven, ~240us). 16 groups x 8 CTAs.
// ---------------------------------------------------------------------------
#define GNC 8
#define GRU_T 384

__global__ __launch_bounds__(GRU_T)
void gru_scan6(const float* __restrict__ gx, const float* __restrict__ Whh,
               const float* __restrict__ bhh, __half* __restrict__ a2)
{
    __shared__ float H_sm[4 * 68];
    __shared__ float gh_sm[96];

    const int j   = blockIdx.x & 7;
    const int bg  = blockIdx.x >> 3;
    const int tid = threadIdx.x;
    const int rh  = tid >> 2;
    const int c   = tid & 3;
    const int gate = rh >> 5;
    const int urow = rh & 31;
    const int grow = gate * HID + j * 32 + urow;

    float w[64];
    {
        const float4* src = (const float4*)(Whh + (size_t)grow * HID + c * 64);
#pragma unroll
        for (int i = 0; i < 16; i++) {
            float4 v = src[i];
            w[4*i] = v.x; w[4*i+1] = v.y; w[4*i+2] = v.z; w[4*i+3] = v.w;
        }
    }

    const int uid = j * 32 + tid;
    float br = 0.f, bz = 0.f, bn = 0.f;
    if (tid < 32) { br = bhh[uid]; bz = bhh[HID + uid]; bn = bhh[2 * HID + uid]; }

    for (int i = tid; i < 4 * 68; i += GRU_T) H_sm[i] = 0.f;
    __syncthreads();

    for (int t = 0; t < SEQ; t++) {
        float xr = 0.f, xz = 0.f, xn = 0.f;
        if (tid < 32) {
            const float* p = gx + (size_t)(bg * SEQ + t) * GATES;
            xr = p[uid]; xz = p[HID + uid]; xn = p[2 * HID + uid];
        }

        const float* hB = &H_sm[c * 68];
        float s0 = 0.f, s1 = 0.f, s2 = 0.f, s3 = 0.f;
#pragma unroll
        for (int i = 0; i < 16; i++) {
            float4 h = *(const float4*)&hB[4 * i];
            s0 += w[4*i]   * h.x; s1 += w[4*i+1] * h.y;
            s2 += w[4*i+2] * h.z; s3 += w[4*i+3] * h.w;
        }
        float s = (s0 + s1) + (s2 + s3);
        s += __shfl_down_sync(0xffffffffu, s, 1, 4);
        s += __shfl_down_sync(0xffffffffu, s, 2, 4);
        if (c == 0) gh_sm[rh] = s;
        __syncthreads();

        if (tid < 32) {
            float hr = gh_sm[tid]      + br;
            float hz = gh_sm[32 + tid] + bz;
            float hn = gh_sm[64 + tid] + bn;
            float hp = H_sm[(uid >> 6) * 68 + (uid & 63)];
            float r = __fdividef(1.f, 1.f + __expf(-(xr + hr)));
            float z = __fdividef(1.f, 1.f + __expf(-(xz + hz)));
            float targ = xn + r * hn;
            targ = fminf(15.f, fmaxf(-15.f, targ));
            float e2 = __expf(2.f * targ);
            float n = 1.f - __fdividef(2.f, e2 + 1.f);
            float hnew = (1.f - z) * n + z * hp;
            g_hbuf[t & 1][bg * HID + uid] = hnew;
            a2[(size_t)(bg * SEQ + t) * HID + uid] = __float2half_rn(hnew);
        }
        __syncthreads();

        if (tid == 0)
            asm volatile("st.release.gpu.u32 [%0], %1;"
                         :: "l"(&g_flags[bg][j]), "r"(t + 1) : "memory");
        if (tid < GNC) {
            int v;
            do {
                asm volatile("ld.acquire.gpu.u32 %0, [%1];"
                             : "=r"(v) : "l"(&g_flags[bg][tid]) : "memory");
            } while (v < t + 1);
        }
        __syncthreads();

        if (tid < 64) {
            int k4 = tid * 4;
            const float4* src = (const float4*)&g_hbuf[t & 1][bg * HID + k4];
            float4 v;
            asm volatile("ld.global.cg.v4.f32 {%0,%1,%2,%3}, [%4];"
                         : "=f"(v.x), "=f"(v.y), "=f"(v.z), "=f"(v.w) : "l"(src));
            float* d = &H_sm[(k4 >> 6) * 68 + (k4 & 63)];
            d[0] = v.x; d[1] = v.y; d[2] = v.z; d[3] = v.w;
        }
        __syncthreads();
    }
}

// ---------------------------------------------------------------------------
// Stage 3: LM head via HMMA fp16, K=256. CTA tile 128x256, 16 warps of the
// PROVEN 64x32 warp tile (2 m x 8 n). Same 2-stage cp.async pipeline; 25%
// fewer cp.async ops per output than the 128x128 config.
// ---------------------------------------------------------------------------
#define LM_BK 64
#define LM_NT (HID / LM_BK)           // 4
#define LM_A_B 16384                  // 128 rows * 128B
#define LM_B_B 32768                  // 256 rows * 128B
#define LM_STAGE_B (LM_A_B + LM_B_B)  // 49152
#define LM_SMEM (2 * LM_STAGE_B)      // 98304
#define LM_T 512

__device__ __forceinline__ void cp16(uint32_t saddr, const void* gaddr) {
    asm volatile("cp.async.cg.shared.global [%0], [%1], 16;"
                 :: "r"(saddr), "l"(gaddr));
}

__global__ __launch_bounds__(LM_T, 1)
void lm_head_hmma(const __half* __restrict__ A2,
                  const __half* __restrict__ B2,
                  float* __restrict__ out)
{
    extern __shared__ char smem[];
    const uint32_t sbase = smem_to_u32(smem);

    const int tid = threadIdx.x;
    const int lane = tid & 31;
    const int wid = tid >> 5;               // 0..15
    const int m0 = blockIdx.x * 128;
    const int n0 = blockIdx.y * 256;
    const int wm = (wid & 1) * 64;          // 2 m-warps
    const int wn = (wid >> 1) * 32;         // 8 n-warps

    const int lg = lane >> 3, lr = lane & 7;
    const int row16 = ((lg & 1) << 3) + lr;
    const int csel  = lg >> 1;

    float acc[4][4][4];
#pragma unroll
    for (int i = 0; i < 4; i++)
#pragma unroll
        for (int j = 0; j < 4; j++)
#pragma unroll
            for (int k = 0; k < 4; k++) acc[i][j][k] = 0.f;

    auto issue = [&](int kt) {
        const uint32_t stage = sbase + (kt & 1) * LM_STAGE_B;
#pragma unroll
        for (int i = 0; i < 2; i++) {       // A: 1024 chunks
            int q = i * LM_T + tid;
            int row = q >> 3, c = q & 7;
            uint32_t soff = row * 128 + (((uint32_t)(c ^ (row & 7))) << 4);
            cp16(stage + soff,
                 A2 + (size_t)(m0 + row) * HID + kt * LM_BK + c * 8);
        }
#pragma unroll
        for (int i = 0; i < 4; i++) {       // B: 2048 chunks
            int q = i * LM_T + tid;
            int row = q >> 3, c = q & 7;
            uint32_t soff = row * 128 + (((uint32_t)(c ^ (row & 7))) << 4);
            cp16(stage + LM_A_B + soff,
                 B2 + (size_t)(n0 + row) * HID + kt * LM_BK + c * 8);
        }
        asm volatile("cp.async.commit_group;" ::: "memory");
    };

    issue(0);

    for (int kt = 0; kt < LM_NT; kt++) {
        if (kt + 1 < LM_NT) {
            issue(kt + 1);
            asm volatile("cp.async.wait_group 1;" ::: "memory");
        } else {
            asm volatile("cp.async.wait_group 0;" ::: "memory");
        }
        __syncthreads();

        const uint32_t Ab = sbase + (kt & 1) * LM_STAGE_B;
        const uint32_t Bb = Ab + LM_A_B;

#pragma unroll
        for (int ks = 0; ks < 4; ks++) {
            const int kc = ks * 2;
            uint32_t a[4][4];
#pragma unroll
            for (int mt = 0; mt < 4; mt++) {
                int row = wm + mt * 16 + row16;
                uint32_t addr = Ab + row * 128 +
                    (((uint32_t)((kc + csel) ^ (row & 7))) << 4);
                asm volatile(
                    "ldmatrix.sync.aligned.m8n8.x4.shared.b16 {%0,%1,%2,%3}, [%4];"
                    : "=r"(a[mt][0]), "=r"(a[mt][1]), "=r"(a[mt][2]), "=r"(a[mt][3])
                    : "r"(addr));
            }
            uint32_t bf[4][2];
#pragma unroll
            for (int np = 0; np < 2; np++) {
                int row = wn + np * 16 + row16;
                uint32_t addr = Bb + row * 128 +
                    (((uint32_t)((kc + csel) ^ (row & 7))) << 4);
                uint32_t q0, q1, q2, q3;
                asm volatile(
                    "ldmatrix.sync.aligned.m8n8.x4.shared.b16 {%0,%1,%2,%3}, [%4];"
                    : "=r"(q0), "=r"(q1), "=r"(q2), "=r"(q3)
                    : "r"(addr));
                bf[np * 2][0] = q0;     bf[np * 2][1] = q2;
                bf[np * 2 + 1][0] = q1; bf[np * 2 + 1][1] = q3;
            }
#pragma unroll
            for (int mt = 0; mt < 4; mt++)
#pragma unroll
                for (int nt = 0; nt < 4; nt++) {
                    asm volatile(
                        "mma.sync.aligned.m16n8k16.row.col.f32.f16.f16.f32 "
                        "{%0,%1,%2,%3}, {%4,%5,%6,%7}, {%8,%9}, {%0,%1,%2,%3};"
                        : "+f"(acc[mt][nt][0]), "+f"(acc[mt][nt][1]),
                          "+f"(acc[mt][nt][2]), "+f"(acc[mt][nt][3])
                        : "r"(a[mt][0]), "r"(a[mt][1]), "r"(a[mt][2]), "r"(a[mt][3]),
                          "r"(bf[nt][0]), "r"(bf[nt][1]));
                }
        }
        __syncthreads();
    }

    const int elr = lane >> 2;
    const int elc = (lane & 3) * 2;
    const bool full = (n0 + 256 <= VOCAB);
#pragma unroll
    for (int mt = 0; mt < 4; mt++) {
#pragma unroll
        for (int nt = 0; nt < 4; nt++) {
            int gr = m0 + wm + mt * 16 + elr;
            int gc = n0 + wn + nt * 8 + elc;
            float* p0 = out + (size_t)gr * VOCAB + gc;
            float* p1 = out + (size_t)(gr + 8) * VOCAB + gc;
            if (full) {
                p0[0] = acc[mt][nt][0]; p0[1] = acc[mt][nt][1];
                p1[0] = acc[mt][nt][2]; p1[1] = acc[mt][nt][3];
            } else {
                if (gc < VOCAB)     { p0[0] = acc[mt][nt][0]; p1[0] = acc[mt][nt][2]; }
                if (gc + 1 < VOCAB) { p0[1] = acc[mt][nt][1]; p1[1] = acc[mt][nt][3]; }
            }
        }
    }
}

// ---------------------------------------------------------------------------
// Launch
// ---------------------------------------------------------------------------
extern "C" void kernel_launch(void* const* d_in, const int* in_sizes, int n_in,
                              void* d_out, int out_size)
{
    const int*   ids   = (const int*)  d_in[0];
    const float* embed = (const float*)d_in[1];
    const float* W_ih  = (const float*)d_in[2];
    const float* b_ih  = (const float*)d_in[3];
    const float* W_hh  = (const float*)d_in[4];
    const float* b_hh  = (const float*)d_in[5];
    const float* W_out = (const float*)d_in[6];
    float* out = (float*)d_out;

    float* gx_ptr;
    __half *a2_ptr, *b2_ptr;
    void* flags_ptr;
    cudaGetSymbolAddress((void**)&gx_ptr, g_gx);
    cudaGetSymbolAddress((void**)&a2_ptr, g_a2);
    cudaGetSymbolAddress((void**)&b2_ptr, g_b2);
    cudaGetSymbolAddress(&flags_ptr, g_flags);

    cudaFuncSetAttribute(lm_head_hmma,
                         cudaFuncAttributeMaxDynamicSharedMemorySize, LM_SMEM);

    // reset barrier flags (graph-capturable memset node)
    cudaMemsetAsync(flags_ptr, 0, sizeof(int) * 16 * 32);

    // 0+1) fused: gx = embed[ids] @ W_ih^T + b_ih  ||  B2 = fp16(W_out)
    fat_gemm_conv<<<FAT_GEMM_CTAS + FAT_CONV_CTAS, 256>>>(
        embed, ids, W_ih, b_ih, gx_ptr, W_out, b2_ptr);

    // 2) GRU scan v6 (16 groups x 8 CTAs)
    gru_scan6<<<128, GRU_T>>>(gx_ptr, W_hh, b_hh, a2_ptr);

    // 3) LM head: 128x256 CTA tile, 16 warps of 64x32
    {
        dim3 grid(MTOK / 128, NPAD / 256);
        lm_head_hmma<<<grid, LM_T, LM_SMEM>>>(a2_ptr, b2_ptr, out);
    }
}

// round 17
// speedup vs baseline: 1.2445x; 1.2445x over previous
#include <cuda_runtime.h>
#include <cuda_fp16.h>
#include <math.h>
#include <stdint.h>

// Problem constants
#define VOCAB 50257
#define NPAD  50304              // 393 * 128
#define DMODEL 128
#define HID 256
#define BATCH 16
#define SEQ 128
#define GATES (3*HID)            // 768
#define MTOK (BATCH*SEQ)         // 2048

// Scratch (__device__ globals per allocation-free rule)
__device__ float g_gx[MTOK * GATES];               // input-side gate projections
__device__ __half g_a2[MTOK * HID];                // fp16(h)    [2048,256]
__device__ __half g_b2[NPAD * HID];                // fp16(W_out)[50304,256]
__device__ unsigned long long g_ht[2][BATCH * HID]; // tagged h exchange (val|tag<<32)

__device__ __forceinline__ uint32_t smem_to_u32(const void* p) {
    uint32_t a;
    asm("{ .reg .u64 t; cvta.to.shared.u64 t, %1; cvt.u32.u64 %0, t; }"
        : "=r"(a) : "l"(p));
    return a;
}

// ---------------------------------------------------------------------------
// Stage 0+1 fused: CTAs 0..95 gather+bias TN SGEMM; CTAs 96..159 W_out->fp16.
// (proven, 50us)
// ---------------------------------------------------------------------------
#define FAT_GEMM_CTAS 96
#define FAT_CONV_CTAS 64

__global__ __launch_bounds__(256)
void fat_gemm_conv(const float* __restrict__ A, const int* __restrict__ idx,
                   const float* __restrict__ Bm, const float* __restrict__ bias,
                   float* __restrict__ C,
                   const float* __restrict__ W, __half* __restrict__ B2)
{
    constexpr int BM = 128, BN = 128, BK = 16;
    constexpr int K = DMODEL;
    __shared__ float As[BK][BM];
    __shared__ float Bs[BK][BN];

    const int tid = threadIdx.x;

    if (blockIdx.x >= FAT_GEMM_CTAS) {
        const int cidx = blockIdx.x - FAT_GEMM_CTAS;
        for (int i = cidx * 256 + tid; i < NPAD * 64; i += FAT_CONV_CTAS * 256) {
            int v = i >> 6;
            int k4 = (i & 63) * 4;
            __half2 h01, h23;
            if (v < VOCAB) {
                float4 x = *(const float4*)(W + (size_t)v * HID + k4);
                h01 = __halves2half2(__float2half_rn(x.x), __float2half_rn(x.y));
                h23 = __halves2half2(__float2half_rn(x.z), __float2half_rn(x.w));
            } else {
                h01 = h23 = __halves2half2(__float2half_rn(0.f), __float2half_rn(0.f));
            }
            __half2* row = (__half2*)(B2 + (size_t)v * HID);
            row[(k4 >> 1)]     = h01;
            row[(k4 >> 1) + 1] = h23;
        }
        return;
    }

    const int tx = tid & 15, ty = tid >> 4;
    const int m0 = (blockIdx.x / 6) * BM, n0 = (blockIdx.x % 6) * BN;

    int a_row[2], a_col[2], b_row[2], b_col[2];
    const float* a_src[2];
    const float* b_src[2];
#pragma unroll
    for (int i = 0; i < 2; i++) {
        int f = tid * 2 + i;
        int r = f >> 2, cv = (f & 3) * 4;
        a_row[i] = r; a_col[i] = cv;
        b_row[i] = r; b_col[i] = cv;
        int gm = m0 + r;
        int src_row = idx[gm];
        a_src[i] = A + (size_t)src_row * K + cv;
        int gn = n0 + r;
        b_src[i] = Bm + (size_t)gn * K + cv;
    }

    float acc[8][8];
#pragma unroll
    for (int i = 0; i < 8; i++)
#pragma unroll
        for (int j = 0; j < 8; j++) acc[i][j] = 0.f;

    const int ntiles = K / BK;
    float4 a_reg[2], b_reg[2];
#pragma unroll
    for (int i = 0; i < 2; i++) {
        a_reg[i] = *(const float4*)(a_src[i]);
        b_reg[i] = *(const float4*)(b_src[i]);
    }

    for (int kt = 0; kt < ntiles; kt++) {
#pragma unroll
        for (int i = 0; i < 2; i++) {
            As[a_col[i]+0][a_row[i]] = a_reg[i].x;
            As[a_col[i]+1][a_row[i]] = a_reg[i].y;
            As[a_col[i]+2][a_row[i]] = a_reg[i].z;
            As[a_col[i]+3][a_row[i]] = a_reg[i].w;
            Bs[b_col[i]+0][b_row[i]] = b_reg[i].x;
            Bs[b_col[i]+1][b_row[i]] = b_reg[i].y;
            Bs[b_col[i]+2][b_row[i]] = b_reg[i].z;
            Bs[b_col[i]+3][b_row[i]] = b_reg[i].w;
        }
        __syncthreads();

        if (kt + 1 < ntiles) {
            int koff = (kt + 1) * BK;
#pragma unroll
            for (int i = 0; i < 2; i++) {
                a_reg[i] = *(const float4*)(a_src[i] + koff);
                b_reg[i] = *(const float4*)(b_src[i] + koff);
            }
        }

#pragma unroll
        for (int k = 0; k < BK; k++) {
            float4 a0 = *(const float4*)&As[k][ty * 8];
            float4 a1 = *(const float4*)&As[k][ty * 8 + 4];
            float4 b0 = *(const float4*)&Bs[k][tx * 8];
            float4 b1 = *(const float4*)&Bs[k][tx * 8 + 4];
            float av[8] = {a0.x,a0.y,a0.z,a0.w,a1.x,a1.y,a1.z,a1.w};
            float bv[8] = {b0.x,b0.y,b0.z,b0.w,b1.x,b1.y,b1.z,b1.w};
#pragma unroll
            for (int i = 0; i < 8; i++)
#pragma unroll
                for (int j = 0; j < 8; j++)
                    acc[i][j] += av[i] * bv[j];
        }
        __syncthreads();
    }

#pragma unroll
    for (int i = 0; i < 8; i++) {
        int gm = m0 + ty * 8 + i;
        float* crow = C + (size_t)gm * GATES + n0 + tx * 8;
#pragma unroll
        for (int j = 0; j < 8; j++) {
            int gn = n0 + tx * 8 + j;
            crow[j] = acc[i][j] + bias[gn];
        }
    }
}

// ---------------------------------------------------------------------------
// Stage 2: GRU scan v9 — tagged-payload exchange. 16 groups (one batch each)
// x 8 CTAs. Each update thread publishes (h | (t+1)<<32) with st.release;
// consumers spin on ld.acquire of their 2 distinct slots. One L2 round-trip
// per step instead of flag-barrier + separate reload.
// ---------------------------------------------------------------------------
#define GRU_T 384

__global__ __launch_bounds__(GRU_T)
void gru_scan9(const float* __restrict__ gx, const float* __restrict__ Whh,
               const float* __restrict__ bhh, __half* __restrict__ a2)
{
    __shared__ float H_sm[4 * 68];          // 4 chunks of 64 units, stride 68
    __shared__ float gh_sm[96];

    const int j   = blockIdx.x & 7;         // CTA in group
    const int bg  = blockIdx.x >> 3;        // batch (group) 0..15
    const int tid = threadIdx.x;
    const int rh  = tid >> 2;               // 0..95 local gate-row
    const int c   = tid & 3;                // k-chunk
    const int gate = rh >> 5;
    const int urow = rh & 31;
    const int grow = gate * HID + j * 32 + urow;

    // Register-resident W chunk (64 floats)
    float w[64];
    {
        const float4* src = (const float4*)(Whh + (size_t)grow * HID + c * 64);
#pragma unroll
        for (int i = 0; i < 16; i++) {
            float4 v = src[i];
            w[4*i] = v.x; w[4*i+1] = v.y; w[4*i+2] = v.z; w[4*i+3] = v.w;
        }
    }

    const int uid = j * 32 + tid;           // (update role, tid < 32)
    float br = 0.f, bz = 0.f, bn = 0.f;
    if (tid < 32) { br = bhh[uid]; bz = bhh[HID + uid]; bn = bhh[2 * HID + uid]; }

    // consumer role (tid < 128): two slots
    const int u0 = tid * 2, u1 = tid * 2 + 1;

    for (int i = tid; i < 4 * 68; i += GRU_T) H_sm[i] = 0.f;
    __syncthreads();

    for (int t = 0; t < SEQ; t++) {
        // prefetch gx operands (overlaps dot)
        float xr = 0.f, xz = 0.f, xn = 0.f;
        if (tid < 32) {
            const float* p = gx + (size_t)(bg * SEQ + t) * GATES;
            xr = p[uid]; xz = p[HID + uid]; xn = p[2 * HID + uid];
        }

        // partial dot over this thread's k-chunk
        const float* hB = &H_sm[c * 68];
        float s0 = 0.f, s1 = 0.f, s2 = 0.f, s3 = 0.f;
#pragma unroll
        for (int i = 0; i < 16; i++) {
            float4 h = *(const float4*)&hB[4 * i];
            s0 += w[4*i]   * h.x; s1 += w[4*i+1] * h.y;
            s2 += w[4*i+2] * h.z; s3 += w[4*i+3] * h.w;
        }
        float s = (s0 + s1) + (s2 + s3);
        s += __shfl_down_sync(0xffffffffu, s, 1, 4);
        s += __shfl_down_sync(0xffffffffu, s, 2, 4);
        if (c == 0) gh_sm[rh] = s;
        __syncthreads();

        if (tid < 32) {
            float hr = gh_sm[tid]      + br;
            float hz = gh_sm[32 + tid] + bz;
            float hn = gh_sm[64 + tid] + bn;
            float hp = H_sm[(uid >> 6) * 68 + (uid & 63)];
            float r = __fdividef(1.f, 1.f + __expf(-(xr + hr)));
            float z = __fdividef(1.f, 1.f + __expf(-(xz + hz)));
            float targ = xn + r * hn;
            targ = fminf(15.f, fmaxf(-15.f, targ));
            float e2 = __expf(2.f * targ);
            float n = 1.f - __fdividef(2.f, e2 + 1.f);
            float hnew = (1.f - z) * n + z * hp;
            a2[(size_t)(bg * SEQ + t) * HID + uid] = __float2half_rn(hnew);
            // publish tagged payload: one release store = signal + data
            unsigned long long pk = (unsigned long long)__float_as_uint(hnew)
                                  | ((unsigned long long)(unsigned)(t + 1) << 32);
            asm volatile("st.release.gpu.u64 [%0], %1;"
                         :: "l"(&g_ht[t & 1][bg * HID + uid]), "l"(pk) : "memory");
        }
        __syncthreads();   // protect H_sm (update read hp) before refresh writes

        // consumers: spin on own 2 slots until tag >= t+1, write into H_sm
        if (tid < 128) {
            const unsigned long long* base = &g_ht[t & 1][bg * HID];
            const unsigned tag = (unsigned)(t + 1);
            unsigned long long v0, v1;
            do {
                asm volatile("ld.acquire.gpu.u64 %0, [%1];"
                             : "=l"(v0) : "l"(base + u0) : "memory");
            } while ((unsigned)(v0 >> 32) < tag);
            do {
                asm volatile("ld.acquire.gpu.u64 %0, [%1];"
                             : "=l"(v1) : "l"(base + u1) : "memory");
            } while ((unsigned)(v1 >> 32) < tag);
            H_sm[(u0 >> 6) * 68 + (u0 & 63)] = __uint_as_float((unsigned)v0);
            H_sm[(u1 >> 6) * 68 + (u1 & 63)] = __uint_as_float((unsigned)v1);
        }
        __syncthreads();
    }
}

// ---------------------------------------------------------------------------
// Stage 3: LM head via HMMA fp16, single-term, K=256.  EXACT R9 kernel
// (measured 290us twice). CTA 128x128, 8 warps (2x4), warp 64x32, BK=64,
// cp.async 2-stage. FROZEN.
// ---------------------------------------------------------------------------
#define LM_BK 64
#define LM_NT (HID / LM_BK)           // 4
#define LM_TILE_B 16384               // 128 rows * 128B
#define LM_STAGE_B (2 * LM_TILE_B)
#define LM_SMEM (2 * LM_STAGE_B)      // 65536

__device__ __forceinline__ void cp16(uint32_t saddr, const void* gaddr) {
    asm volatile("cp.async.cg.shared.global [%0], [%1], 16;"
                 :: "r"(saddr), "l"(gaddr));
}

__global__ __launch_bounds__(256, 2)
void lm_head_hmma(const __half* __restrict__ A2,
                  const __half* __restrict__ B2,
                  float* __restrict__ out)
{
    extern __shared__ char smem[];
    const uint32_t sbase = smem_to_u32(smem);

    const int tid = threadIdx.x;
    const int lane = tid & 31;
    const int wid = tid >> 5;
    const int m0 = blockIdx.x * 128;
    const int n0 = blockIdx.y * 128;
    const int wm = (wid >> 2) * 64;
    const int wn = (wid & 3) * 32;

    const int lg = lane >> 3, lr = lane & 7;
    const int row16 = ((lg & 1) << 3) + lr;
    const int csel  = lg >> 1;

    float acc[4][4][4];
#pragma unroll
    for (int i = 0; i < 4; i++)
#pragma unroll
        for (int j = 0; j < 4; j++)
#pragma unroll
            for (int k = 0; k < 4; k++) acc[i][j][k] = 0.f;

    auto issue = [&](int kt) {
        const uint32_t stage = sbase + (kt & 1) * LM_STAGE_B;
#pragma unroll
        for (int i = 0; i < 4; i++) {
            int q = i * 256 + tid;
            int row = q >> 3, c = q & 7;
            uint32_t soff = row * 128 + (((uint32_t)(c ^ (row & 7))) << 4);
            cp16(stage + soff,
                 A2 + (size_t)(m0 + row) * HID + kt * LM_BK + c * 8);
            cp16(stage + LM_TILE_B + soff,
                 B2 + (size_t)(n0 + row) * HID + kt * LM_BK + c * 8);
        }
        asm volatile("cp.async.commit_group;" ::: "memory");
    };

    issue(0);

    for (int kt = 0; kt < LM_NT; kt++) {
        if (kt + 1 < LM_NT) {
            issue(kt + 1);
            asm volatile("cp.async.wait_group 1;" ::: "memory");
        } else {
            asm volatile("cp.async.wait_group 0;" ::: "memory");
        }
        __syncthreads();

        const uint32_t Ab = sbase + (kt & 1) * LM_STAGE_B;
        const uint32_t Bb = Ab + LM_TILE_B;

#pragma unroll
        for (int ks = 0; ks < 4; ks++) {
            const int kc = ks * 2;
            uint32_t a[4][4];
#pragma unroll
            for (int mt = 0; mt < 4; mt++) {
                int row = wm + mt * 16 + row16;
                uint32_t addr = Ab + row * 128 +
                    (((uint32_t)((kc + csel) ^ (row & 7))) << 4);
                asm volatile(
                    "ldmatrix.sync.aligned.m8n8.x4.shared.b16 {%0,%1,%2,%3}, [%4];"
                    : "=r"(a[mt][0]), "=r"(a[mt][1]), "=r"(a[mt][2]), "=r"(a[mt][3])
                    : "r"(addr));
            }
            uint32_t bf[4][2];
#pragma unroll
            for (int np = 0; np < 2; np++) {
                int row = wn + np * 16 + row16;
                uint32_t addr = Bb + row * 128 +
                    (((uint32_t)((kc + csel) ^ (row & 7))) << 4);
                uint32_t q0, q1, q2, q3;
                asm volatile(
                    "ldmatrix.sync.aligned.m8n8.x4.shared.b16 {%0,%1,%2,%3}, [%4];"
                    : "=r"(q0), "=r"(q1), "=r"(q2), "=r"(q3)
                    : "r"(addr));
                bf[np * 2][0] = q0;     bf[np * 2][1] = q2;
                bf[np * 2 + 1][0] = q1; bf[np * 2 + 1][1] = q3;
            }
#pragma unroll
            for (int mt = 0; mt < 4; mt++)
#pragma unroll
                for (int nt = 0; nt < 4; nt++) {
                    asm volatile(
                        "mma.sync.aligned.m16n8k16.row.col.f32.f16.f16.f32 "
                        "{%0,%1,%2,%3}, {%4,%5,%6,%7}, {%8,%9}, {%0,%1,%2,%3};"
                        : "+f"(acc[mt][nt][0]), "+f"(acc[mt][nt][1]),
                          "+f"(acc[mt][nt][2]), "+f"(acc[mt][nt][3])
                        : "r"(a[mt][0]), "r"(a[mt][1]), "r"(a[mt][2]), "r"(a[mt][3]),
                          "r"(bf[nt][0]), "r"(bf[nt][1]));
                }
        }
        __syncthreads();
    }

    const int elr = lane >> 2;
    const int elc = (lane & 3) * 2;
    const bool full = (n0 + 128 <= VOCAB);
#pragma unroll
    for (int mt = 0; mt < 4; mt++) {
#pragma unroll
        for (int nt = 0; nt < 4; nt++) {
            int gr = m0 + wm + mt * 16 + elr;
            int gc = n0 + wn + nt * 8 + elc;
            float* p0 = out + (size_t)gr * VOCAB + gc;
            float* p1 = out + (size_t)(gr + 8) * VOCAB + gc;
            if (full) {
                p0[0] = acc[mt][nt][0]; p0[1] = acc[mt][nt][1];
                p1[0] = acc[mt][nt][2]; p1[1] = acc[mt][nt][3];
            } else {
                if (gc < VOCAB)     { p0[0] = acc[mt][nt][0]; p1[0] = acc[mt][nt][2]; }
                if (gc + 1 < VOCAB) { p0[1] = acc[mt][nt][1]; p1[1] = acc[mt][nt][3]; }
            }
        }
    }
}

// ---------------------------------------------------------------------------
// Launch
// ---------------------------------------------------------------------------
extern "C" void kernel_launch(void* const* d_in, const int* in_sizes, int n_in,
                              void* d_out, int out_size)
{
    const int*   ids   = (const int*)  d_in[0];
    const float* embed = (const float*)d_in[1];
    const float* W_ih  = (const float*)d_in[2];
    const float* b_ih  = (const float*)d_in[3];
    const float* W_hh  = (const float*)d_in[4];
    const float* b_hh  = (const float*)d_in[5];
    const float* W_out = (const float*)d_in[6];
    float* out = (float*)d_out;

    float* gx_ptr;
    __half *a2_ptr, *b2_ptr;
    void* ht_ptr;
    cudaGetSymbolAddress((void**)&gx_ptr, g_gx);
    cudaGetSymbolAddress((void**)&a2_ptr, g_a2);
    cudaGetSymbolAddress((void**)&b2_ptr, g_b2);
    cudaGetSymbolAddress(&ht_ptr, g_ht);

    cudaFuncSetAttribute(lm_head_hmma,
                         cudaFuncAttributeMaxDynamicSharedMemorySize, LM_SMEM);

    // reset exchange tags (graph-capturable memset node)
    cudaMemsetAsync(ht_ptr, 0, sizeof(unsigned long long) * 2 * BATCH * HID);

    // 0+1) fused: gx = embed[ids] @ W_ih^T + b_ih  ||  B2 = fp16(W_out)
    fat_gemm_conv<<<FAT_GEMM_CTAS + FAT_CONV_CTAS, 256>>>(
        embed, ids, W_ih, b_ih, gx_ptr, W_out, b2_ptr);

    // 2) GRU scan v9 (tagged-payload exchange)
    gru_scan9<<<128, GRU_T>>>(gx_ptr, W_hh, b_hh, a2_ptr);

    // 3) LM head on HMMA fp16 (K=256, 2-stage — frozen R9 config)
    {
        dim3 grid(MTOK / 128, NPAD / 128);
        lm_head_hmma<<<grid, 256, LM_SMEM>>>(a2_ptr, b2_ptr, out);
    }
}